// round 1
// baseline (speedup 1.0000x reference)
#include <cuda_runtime.h>
#include <math.h>

// Problem constants
#define Bc 8
#define Lc 1024
#define Ec 512
#define Hc 8
#define HDc 64
#define Pc 2047
#define BHc (Bc * Hc)

#define OUT_ELEMS  (Bc * Lc * Ec)           /* 4194304  */
#define ATTN_ELEMS (BHc * Lc * Lc)          /* 67108864 */

// Scratch (device globals: allocation-free rule)
__device__ float g_proj[(size_t)Bc * Lc * 3 * Ec];   // (8192, 1536)
__device__ float g_pk[(size_t)Pc * Ec];              // (2047, 512)
__device__ float g_ctx[(size_t)Bc * Lc * Ec];        // (8192, 512)
__device__ float g_attn_scratch[(size_t)ATTN_ELEMS]; // fallback if attn not in d_out

// ---------------------------------------------------------------------------
// Generic SGEMM: C[M,N] = A[M,K] @ W[N,K]^T (+ bias). 64x64 tile, 4x4 micro.
// dst_sel: 0 = C_ext, 1 = g_proj, 2 = g_pk. src_sel: 0 = A_ext, 1 = g_ctx.
// ---------------------------------------------------------------------------
__global__ void sgemm_nt(const float* __restrict__ A_ext, int src_sel,
                         const float* __restrict__ W,
                         const float* __restrict__ bias,
                         float* __restrict__ C_ext, int dst_sel,
                         int M, int N, int K) {
    const float* A = (src_sel == 1) ? g_ctx : A_ext;
    float* C = (dst_sel == 1) ? g_proj : (dst_sel == 2) ? g_pk : C_ext;

    __shared__ float As[16][65];
    __shared__ float Ws[16][65];

    const int tid = threadIdx.x;
    const int tx = tid & 15;        // n micro group
    const int ty = tid >> 4;        // m micro group
    const int m0 = blockIdx.y << 6;
    const int n0 = blockIdx.x << 6;

    const int lr = tid >> 2;        // 0..63: row within tile for loading
    const int lk = (tid & 3) << 2;  // 0,4,8,12: k offset for float4 load

    float acc[4][4];
#pragma unroll
    for (int i = 0; i < 4; i++)
#pragma unroll
        for (int j = 0; j < 4; j++) acc[i][j] = 0.f;

    for (int k0 = 0; k0 < K; k0 += 16) {
        float4 av = make_float4(0.f, 0.f, 0.f, 0.f);
        float4 wv = make_float4(0.f, 0.f, 0.f, 0.f);
        if (m0 + lr < M)
            av = *reinterpret_cast<const float4*>(&A[(size_t)(m0 + lr) * K + k0 + lk]);
        if (n0 + lr < N)
            wv = *reinterpret_cast<const float4*>(&W[(size_t)(n0 + lr) * K + k0 + lk]);
        __syncthreads();
        As[lk + 0][lr] = av.x; As[lk + 1][lr] = av.y;
        As[lk + 2][lr] = av.z; As[lk + 3][lr] = av.w;
        Ws[lk + 0][lr] = wv.x; Ws[lk + 1][lr] = wv.y;
        Ws[lk + 2][lr] = wv.z; Ws[lk + 3][lr] = wv.w;
        __syncthreads();
#pragma unroll
        for (int kk = 0; kk < 16; kk++) {
            float a[4], w[4];
#pragma unroll
            for (int i = 0; i < 4; i++) a[i] = As[kk][(ty << 2) + i];
#pragma unroll
            for (int j = 0; j < 4; j++) w[j] = Ws[kk][(tx << 2) + j];
#pragma unroll
            for (int i = 0; i < 4; i++)
#pragma unroll
                for (int j = 0; j < 4; j++) acc[i][j] += a[i] * w[j];
        }
    }

#pragma unroll
    for (int i = 0; i < 4; i++) {
        int m = m0 + (ty << 2) + i;
        if (m >= M) continue;
#pragma unroll
        for (int j = 0; j < 4; j++) {
            int n = n0 + (tx << 2) + j;
            if (n < N)
                C[(size_t)m * N + n] = acc[i][j] + (bias ? bias[n] : 0.f);
        }
    }
}

// ---------------------------------------------------------------------------
// Fused attention kernel.
// Grid: (L/64, B*H). Block: 256 threads.
// Phase 1: scores = (q+u)s . k  +  (q+v)s . p_k[k-q+L-1]; write raw to attn
//          buffer; streaming (m,s) per q row.
// Phase 2: normalize -> write attn; ctx = attn @ v accumulated in registers.
// ---------------------------------------------------------------------------
#define SM_QU   0
#define SM_QV   (64 * 65)
#define SM_KT   (2 * 64 * 65)
#define SM_PKT  (3 * 64 * 65)
#define SM_ROWM (3 * 64 * 65 + 128 * 65)
#define SM_ROWS (SM_ROWM + 64)
#define SM_FLOATS (SM_ROWS + 64)
#define SM_BYTES (SM_FLOATS * 4)

__global__ void attn_kernel(const float* __restrict__ ubias,
                            const float* __restrict__ vbias,
                            float* __restrict__ attn_ext, int use_scratch) {
    extern __shared__ float sm[];
    float* QU  = sm + SM_QU;    // (64,65) (q+u)*scale
    float* QV  = sm + SM_QV;    // (64,65) (q+v)*scale
    float* KT  = sm + SM_KT;    // (64,65) k tile; reused as attn tile in phase 2
    float* PKT = sm + SM_PKT;   // (128,65) p_k window; reused as red + v tile
    float* ROWM = sm + SM_ROWM; // (64) row max
    float* ROWS = sm + SM_ROWS; // (64) 1/rowsum

    float* attn = use_scratch ? g_attn_scratch : attn_ext;

    const int tid = threadIdx.x;
    const int tx = tid & 15;     // k (phase1) / d (phase2) micro group
    const int ty = tid >> 4;     // q micro group
    const int bh = blockIdx.y;
    const int b = bh >> 3, h = bh & 7;
    const int q0 = blockIdx.x << 6;
    const int qbase = ty << 2, kbase = tx << 2;
    const float scale = 0.04419417382415922f;  // 1/sqrt(512)

    // Load (q+u)*scale and (q+v)*scale tiles
    for (int idx = tid; idx < 64 * 64; idx += 256) {
        int qq = idx >> 6, d = idx & 63;
        float qval = g_proj[((size_t)(b * Lc + q0 + qq)) * 1536 + h * 192 + d];
        QU[qq * 65 + d] = (qval + ubias[h * 64 + d]) * scale;
        QV[qq * 65 + d] = (qval + vbias[h * 64 + d]) * scale;
    }

    float m_run[4], s_run[4];
#pragma unroll
    for (int i = 0; i < 4; i++) { m_run[i] = -INFINITY; s_run[i] = 0.f; }

    // ---------------- Phase 1: scores + streaming softmax stats -------------
    for (int kt0 = 0; kt0 < Lc; kt0 += 64) {
        __syncthreads();
        // k tile
        for (int idx = tid; idx < 64 * 64; idx += 256) {
            int kk = idx >> 6, d = idx & 63;
            KT[kk * 65 + d] =
                g_proj[((size_t)(b * Lc + kt0 + kk)) * 1536 + h * 192 + 64 + d];
        }
        // p_k window: rows pbase .. pbase+127 cover all (q,k) pairs in tile
        int pbase = kt0 - q0 + 960;
        for (int idx = tid; idx < 128 * 64; idx += 256) {
            int r = idx >> 6, d = idx & 63;
            int pr = pbase + r;
            PKT[r * 65 + d] =
                (pr >= 0 && pr < Pc) ? g_pk[(size_t)pr * 512 + h * 64 + d] : 0.f;
        }
        __syncthreads();

        float sc[4][4];
#pragma unroll
        for (int i = 0; i < 4; i++)
#pragma unroll
            for (int j = 0; j < 4; j++) sc[i][j] = 0.f;

        // ac: (q+u)s . k
#pragma unroll 4
        for (int d = 0; d < 64; d++) {
            float a[4], kb[4];
#pragma unroll
            for (int i = 0; i < 4; i++) a[i] = QU[(qbase + i) * 65 + d];
#pragma unroll
            for (int j = 0; j < 4; j++) kb[j] = KT[(kbase + j) * 65 + d];
#pragma unroll
            for (int i = 0; i < 4; i++)
#pragma unroll
                for (int j = 0; j < 4; j++) sc[i][j] += a[i] * kb[j];
        }
        // bd: (q+v)s . p_k[k-q+1023]; smem row = (kk - qq) + 63
        const int r0 = kbase - qbase + 63;  // 3..123, need rows r0-3..r0+3
#pragma unroll 4
        for (int d = 0; d < 64; d++) {
            float av[4], pv[7];
#pragma unroll
            for (int i = 0; i < 4; i++) av[i] = QV[(qbase + i) * 65 + d];
#pragma unroll
            for (int t = 0; t < 7; t++) pv[t] = PKT[(r0 - 3 + t) * 65 + d];
#pragma unroll
            for (int i = 0; i < 4; i++)
#pragma unroll
                for (int j = 0; j < 4; j++) sc[i][j] += av[i] * pv[j - i + 3];
        }

        // Write raw scores; update per-thread streaming (m,s)
#pragma unroll
        for (int i = 0; i < 4; i++) {
            float* rowp = attn + ((size_t)bh * Lc + (q0 + qbase + i)) * Lc + kt0 + kbase;
            float mloc = fmaxf(fmaxf(sc[i][0], sc[i][1]), fmaxf(sc[i][2], sc[i][3]));
            float mnew = fmaxf(m_run[i], mloc);
            float sl = 0.f;
#pragma unroll
            for (int j = 0; j < 4; j++) {
                rowp[j] = sc[i][j];
                sl += __expf(sc[i][j] - mnew);
            }
            s_run[i] = s_run[i] * __expf(m_run[i] - mnew) + sl;
            m_run[i] = mnew;
        }
    }

    // Combine (m,s) across the 16 tx groups per q row
    __syncthreads();
    float* redm = PKT;          // 64*16
    float* reds = PKT + 1024;   // 64*16
#pragma unroll
    for (int i = 0; i < 4; i++) {
        redm[(qbase + i) * 16 + tx] = m_run[i];
        reds[(qbase + i) * 16 + tx] = s_run[i];
    }
    __syncthreads();
    if (tid < 64) {
        float m = -INFINITY;
#pragma unroll
        for (int t = 0; t < 16; t++) m = fmaxf(m, redm[tid * 16 + t]);
        float s = 0.f;
#pragma unroll
        for (int t = 0; t < 16; t++)
            s += reds[tid * 16 + t] * __expf(redm[tid * 16 + t] - m);
        ROWM[tid] = m;
        ROWS[tid] = 1.f / s;
    }

    // ---------------- Phase 2: normalize attn, ctx = attn @ v ---------------
    float co[4][4];
#pragma unroll
    for (int i = 0; i < 4; i++)
#pragma unroll
        for (int j = 0; j < 4; j++) co[i][j] = 0.f;

    for (int kt0 = 0; kt0 < Lc; kt0 += 64) {
        __syncthreads();
        // attn tile: read raw score, normalize, write back + keep in smem
        for (int idx = tid; idx < 64 * 64; idx += 256) {
            int qq = idx >> 6, kk = idx & 63;
            size_t gi = ((size_t)bh * Lc + (q0 + qq)) * Lc + kt0 + kk;
            float a = __expf(attn[gi] - ROWM[qq]) * ROWS[qq];
            attn[gi] = a;
            KT[qq * 65 + kk] = a;
        }
        // v tile
        for (int idx = tid; idx < 64 * 64; idx += 256) {
            int kk = idx >> 6, d = idx & 63;
            PKT[kk * 65 + d] =
                g_proj[((size_t)(b * Lc + kt0 + kk)) * 1536 + h * 192 + 128 + d];
        }
        __syncthreads();
#pragma unroll 4
        for (int kk = 0; kk < 64; kk++) {
            float a[4], vv[4];
#pragma unroll
            for (int i = 0; i < 4; i++) a[i] = KT[(qbase + i) * 65 + kk];
#pragma unroll
            for (int j = 0; j < 4; j++) vv[j] = PKT[kk * 65 + kbase + j];
#pragma unroll
            for (int i = 0; i < 4; i++)
#pragma unroll
                for (int j = 0; j < 4; j++) co[i][j] += a[i] * vv[j];
        }
    }

#pragma unroll
    for (int i = 0; i < 4; i++)
#pragma unroll
        for (int j = 0; j < 4; j++)
            g_ctx[((size_t)(b * Lc + q0 + qbase + i)) * 512 + h * 64 + kbase + j] =
                co[i][j];
}

// ---------------------------------------------------------------------------
extern "C" void kernel_launch(void* const* d_in, const int* in_sizes, int n_in,
                              void* d_out, int out_size) {
    const float* x    = (const float*)d_in[0];  // (8,1024,512)
    const float* pos  = (const float*)d_in[1];  // (1,2047,512)
    const float* wqkv = (const float*)d_in[2];  // (1536,512)
    const float* wpos = (const float*)d_in[3];  // (512,512)
    const float* wout = (const float*)d_in[4];  // (512,512)
    const float* bout = (const float*)d_in[5];  // (512)
    const float* ub   = (const float*)d_in[6];  // (64,8) viewed (8,64)
    const float* vb   = (const float*)d_in[7];  // (64,8) viewed (8,64)
    float* out = (float*)d_out;

    int attn_in_out = ((long long)out_size >= (long long)OUT_ELEMS + ATTN_ELEMS);
    float* attn_buf = attn_in_out ? (out + OUT_ELEMS) : nullptr;

    dim3 blk(256);

    // proj = x @ wqkv^T : (8192,1536)
    sgemm_nt<<<dim3(24, 128), blk>>>(x, 0, wqkv, nullptr, nullptr, 1,
                                     Bc * Lc, 3 * Ec, Ec);
    // p_k = pos @ wpos^T : (2047,512)
    sgemm_nt<<<dim3(8, 32), blk>>>(pos, 0, wpos, nullptr, nullptr, 2,
                                   Pc, Ec, Ec);

    cudaFuncSetAttribute(attn_kernel, cudaFuncAttributeMaxDynamicSharedMemorySize,
                         SM_BYTES);
    attn_kernel<<<dim3(Lc / 64, BHc), blk, SM_BYTES>>>(ub, vb, attn_buf,
                                                       attn_in_out ? 0 : 1);

    // out = ctx @ wout^T + bout : (8192,512)
    sgemm_nt<<<dim3(8, 128), blk>>>(nullptr, 1, wout, bout, out, 0,
                                    Bc * Lc, Ec, Ec);
}